// round 7
// baseline (speedup 1.0000x reference)
#include <cuda_runtime.h>

#define BB 4
#define NPTS 2048
#define HH 128
#define WW 128
#define SPLITS 32
#define KCH (NPTS / SPLITS)   // 64 atoms per block
#define CHUNK 32              // atoms resident in shared at once
#define IMG (BB * HH * WW)    // 65536
#define IMGB (HH * WW)        // 16384 per batch
#define IMGB4 (IMGB / 4)      // 4096 float4 per batch
#define CLEAN_OFF (IMG + 36)  // clean region start in out (float4-aligned)

// Self-cleaning scratch: zero at module load, re-zeroed by finisher each run.
__device__ float g_clean[IMG];
__device__ int   g_cnt[BB];

#define RED4(ptr, v) \
    asm volatile("red.global.add.v4.f32 [%0], {%1,%2,%3,%4};" \
                 :: "l"(ptr), "f"((v).x), "f"((v).y), "f"((v).z), "f"((v).w) \
                 : "memory")

// ---------------------------------------------------------------------------
// Single fused kernel. Block (s, b): sparse outer-product accumulation of its
// 64 atoms into registers, RED.v4 into g_clean[b]. Last block per batch
// (threadfence + counter) computes noisy/clean outputs and re-zeros scratch.
// ---------------------------------------------------------------------------
__global__ void __launch_bounds__(256) fused_kernel(const float* __restrict__ x,
                                                    const float* __restrict__ rot,
                                                    const float* __restrict__ noise,
                                                    float* __restrict__ out) {
    int s = blockIdx.x;
    int b = blockIdx.y;

    __shared__ float sfy[CHUNK][128];     // 16KB
    __shared__ float sfx[CHUNK][128];     // 16KB
    __shared__ float spx[CHUNK];
    __shared__ float spy[CHUNK];
    __shared__ unsigned swm[8];           // per-window atom bitmap
    __shared__ int is_last;

    int tid  = threadIdx.x;
    int w    = tid >> 5;        // warp id = row-window id (0..7)
    int lane = tid & 31;
    int rg   = lane >> 4;       // row sub-group (0/1)
    int cx   = lane & 15;       // column group

    const float* R = rot + b * 9;
    float R0 = R[0], R1 = R[1], R2 = R[2];
    float R3 = R[3], R4 = R[4], R5 = R[5];

    float acc[8][8];
#pragma unroll
    for (int i = 0; i < 8; i++)
#pragma unroll
        for (int j = 0; j < 8; j++) acc[i][j] = 0.0f;

    int atom_base = b * NPTS + s * KCH;

    for (int c = 0; c < KCH / CHUNK; c++) {
        // --- Phase A: warp 0 projects 32 atoms, builds window bitmaps ---
        if (tid < 32) {
            const float* xp = x + (atom_base + c * CHUNK + tid) * 3;
            float x0 = xp[0], x1 = xp[1], x2 = xp[2];
            const float scale = 51.2f;
            float px = fmaf(R0, x0, fmaf(R1, x1, R2 * x2)) * scale + 64.0f;
            float py = fmaf(R3, x0, fmaf(R4, x1, R5 * x2)) * scale + 64.0f;
            spx[tid] = px;
            spy[tid] = py;
            int w0 = (int)floorf((py - 12.0f) * 0.0625f);
            int w1 = (int)floorf((py + 12.0f) * 0.0625f);
            if (w0 < 0) w0 = 0;
            if (w1 > 7) w1 = 7;
#pragma unroll
            for (int ww = 0; ww < 8; ww++) {
                unsigned bm = __ballot_sync(0xffffffffu, ww >= w0 && ww <= w1);
                if (tid == ww) swm[ww] = bm;
            }
        }
        __syncthreads();

        // --- Phase B: factor tables (cutoff d^2>=144 -> exp ~ 1e-14) ---
        const float cexp = -0.22222222f;  // -1/(2*1.5^2)
#pragma unroll 4
        for (int i = 0; i < 16; i++) {
            int e = tid + i * 256;
            int a = e >> 7;
            int p = e & 127;
            float fp = (float)p;
            float dx = fp - spx[a];
            float dy = fp - spy[a];
            float qx = dx * dx;
            float qy = dy * dy;
            sfx[a][p] = (qx < 144.0f) ? __expf(qx * cexp) : 0.0f;
            sfy[a][p] = (qy < 144.0f) ? __expf(qy * cexp) : 0.0f;
        }
        __syncthreads();

        // --- Phase C: sparse rank update (only atoms hitting this window) ---
        unsigned m = swm[w];
        while (m) {
            int kk = __ffs(m) - 1;
            m &= m - 1;
            float yv[8], xv[8];
            *(float4*)&yv[0] = *(float4*)&sfy[kk][16 * w + 8 * rg];
            *(float4*)&yv[4] = *(float4*)&sfy[kk][16 * w + 8 * rg + 4];
            *(float4*)&xv[0] = *(float4*)&sfx[kk][cx * 4];
            *(float4*)&xv[4] = *(float4*)&sfx[kk][64 + cx * 4];
#pragma unroll
            for (int i = 0; i < 8; i++)
#pragma unroll
                for (int j = 0; j < 8; j++)
                    acc[i][j] = fmaf(yv[i], xv[j], acc[i][j]);
        }
        __syncthreads();
    }

    // --- Epilogue: reduce into scratch via L2 atomics ---
    float* dst = g_clean + b * IMGB;
#pragma unroll
    for (int i = 0; i < 8; i++) {
        int h = 16 * w + 8 * rg + i;
#pragma unroll
        for (int jj = 0; jj < 2; jj++) {
            int wc = (jj == 0) ? (cx * 4) : (64 + cx * 4);
            float4 v = make_float4(acc[i][jj * 4 + 0], acc[i][jj * 4 + 1],
                                   acc[i][jj * 4 + 2], acc[i][jj * 4 + 3]);
            RED4(dst + h * WW + wc, v);
        }
    }

    // --- Finisher election: last block of this batch ---
    __threadfence();   // make our REDs visible before the counter increment
    if (tid == 0) {
        int old = atomicAdd(&g_cnt[b], 1);
        is_last = (old == SPLITS - 1);
    }
    __syncthreads();
    if (!is_last) return;
    __threadfence();   // acquire: all 32 blocks' REDs now visible

    const float4* cl4 = (const float4*)(g_clean) + b * IMGB4;
    const float4* nz4 = (const float4*)(noise)   + b * IMGB4;
    float4*       ny4 = (float4*)(out)           + b * IMGB4;
#pragma unroll 4
    for (int t = tid; t < IMGB4; t += 256) {
        float4 sv = __ldcg((const float4*)(cl4 + t));
        float4 nz = nz4[t];
        float4 noisy = make_float4(fmaf(nz.x, 0.1f, sv.x), fmaf(nz.y, 0.1f, sv.y),
                                   fmaf(nz.z, 0.1f, sv.z), fmaf(nz.w, 0.1f, sv.w));
        ny4[t] = noisy;                                      // noisy
        *(float4*)&out[CLEAN_OFF + (b * IMGB4 + t) * 4] = sv; // clean
        ((float4*)g_clean)[b * IMGB4 + t] = make_float4(0.f, 0.f, 0.f, 0.f);
    }
    if (tid < 9) out[IMG + b * 9 + tid] = rot[b * 9 + tid];   // rot passthrough
    if (tid == 0) g_cnt[b] = 0;                               // reset for replay
}

// ---------------------------------------------------------------------------
extern "C" void kernel_launch(void* const* d_in, const int* in_sizes, int n_in,
                              void* d_out, int out_size) {
    const float* x     = (const float*)d_in[0];  // (4,2048,3)
    const float* rot   = (const float*)d_in[1];  // (4,3,3)
    const float* noise = (const float*)d_in[2];  // (4,128,128)
    float* out = (float*)d_out;

    dim3 grid(SPLITS, BB);
    fused_kernel<<<grid, 256>>>(x, rot, noise, out);
}

// round 9
// speedup vs baseline: 1.3264x; 1.3264x over previous
#include <cuda_runtime.h>

#define BB 4
#define NPTS 2048
#define HH 128
#define WW 128
#define SPLITS 32
#define KCH (NPTS / SPLITS)   // 64 atoms per (s,b)
#define CHUNK 32              // atoms resident in shared at once
#define IMG (BB * HH * WW)    // 65536
#define IMG4 (IMG / 4)        // 16384
#define IMGB (HH * WW)        // 16384

// Split-K partials: 32 * 256KB = 8 MB (no device allocations allowed)
__device__ float g_part[SPLITS * BB * HH * WW];

// ---------------------------------------------------------------------------
// Fused kernel, column-halved. Block (s, b, hf) accumulates its 64 atoms into
// output columns [64*hf, 64*hf+64). Warp w owns rows [16w, 16w+16); thread
// tile 8 rows x 4 cols. Atom processed only if its y-support hits the warp's
// window AND its x-support hits this column half (skipped atoms are exactly
// zero on this tile).
// ---------------------------------------------------------------------------
__global__ void __launch_bounds__(256) fused_kernel(const float* __restrict__ x,
                                                    const float* __restrict__ rot) {
    int s  = blockIdx.x;
    int b  = blockIdx.y;
    int hf = blockIdx.z;             // column half (0/1)
    float colbase = 64.0f * hf;

    __shared__ float sfy[CHUNK][128];   // 16KB  (all rows)
    __shared__ float sfx[CHUNK][64];    // 8KB   (this half's cols)
    __shared__ float spx[CHUNK];
    __shared__ float spy[CHUNK];
    __shared__ unsigned swm[8];         // per-row-window atom bitmap
    __shared__ unsigned sxm;            // this-half atom bitmap

    int tid  = threadIdx.x;
    int w    = tid >> 5;      // warp id = 16-row window (0..7)
    int lane = tid & 31;
    int rg   = lane >> 4;     // row sub-group: rows 16w+8rg .. +8
    int cx   = lane & 15;     // 4-col group within the 64-col half

    const float* R = rot + b * 9;
    float R0 = R[0], R1 = R[1], R2 = R[2];
    float R3 = R[3], R4 = R[4], R5 = R[5];

    float acc[8][4];
#pragma unroll
    for (int i = 0; i < 8; i++)
#pragma unroll
        for (int j = 0; j < 4; j++) acc[i][j] = 0.0f;

    int atom_base = b * NPTS + s * KCH;

    for (int c = 0; c < KCH / CHUNK; c++) {
        // --- Phase A: warp 0 projects 32 atoms, builds bitmaps ---
        if (tid < 32) {
            const float* xp = x + (atom_base + c * CHUNK + tid) * 3;
            float x0 = xp[0], x1 = xp[1], x2 = xp[2];
            const float scale = 51.2f;
            float px = fmaf(R0, x0, fmaf(R1, x1, R2 * x2)) * scale + 64.0f;
            float py = fmaf(R3, x0, fmaf(R4, x1, R5 * x2)) * scale + 64.0f;
            spx[tid] = px;
            spy[tid] = py;
            int w0 = (int)floorf((py - 12.0f) * 0.0625f);
            int w1 = (int)floorf((py + 12.0f) * 0.0625f);
            if (w0 < 0) w0 = 0;
            if (w1 > 7) w1 = 7;
#pragma unroll
            for (int ww = 0; ww < 8; ww++) {
                unsigned bm = __ballot_sync(0xffffffffu, ww >= w0 && ww <= w1);
                if (tid == ww) swm[ww] = bm;
            }
            unsigned hx = __ballot_sync(0xffffffffu,
                                        px > colbase - 12.0f && px < colbase + 75.0f);
            if (tid == 0) sxm = hx;
        }
        __syncthreads();

        // --- Phase B: factor tables (cutoff d^2>=144 -> exp ~ 1e-14) ---
        const float cexp = -0.22222222f;  // -1/(2*1.5^2)
        // sfy: 4096 entries (rows 0..127)
#pragma unroll 4
        for (int i = 0; i < 16; i++) {
            int e = tid + i * 256;
            int a = e >> 7;
            int p = e & 127;
            float dy = (float)p - spy[a];
            float qy = dy * dy;
            sfy[a][p] = (qy < 144.0f) ? __expf(qy * cexp) : 0.0f;
        }
        // sfx: 2048 entries (this half's 64 cols)
#pragma unroll 4
        for (int i = 0; i < 8; i++) {
            int e = tid + i * 256;
            int a = e >> 6;
            int pl = e & 63;
            float dx = (colbase + (float)pl) - spx[a];
            float qx = dx * dx;
            sfx[a][pl] = (qx < 144.0f) ? __expf(qx * cexp) : 0.0f;
        }
        __syncthreads();

        // --- Phase C: sparse rank update ---
        unsigned m = swm[w] & sxm;
        int rowbase = 16 * w + 8 * rg;
        while (m) {
            int kk = __ffs(m) - 1;
            m &= m - 1;
            float yv[8], xv[4];
            *(float4*)&yv[0] = *(float4*)&sfy[kk][rowbase];      // broadcast
            *(float4*)&yv[4] = *(float4*)&sfy[kk][rowbase + 4];
            *(float4*)&xv[0] = *(float4*)&sfx[kk][cx * 4];
#pragma unroll
            for (int i = 0; i < 8; i++)
#pragma unroll
                for (int j = 0; j < 4; j++)
                    acc[i][j] = fmaf(yv[i], xv[j], acc[i][j]);
        }
        __syncthreads();
    }

    // --- Epilogue: store this half's partial tile ---
    float* out = g_part + (s * BB + b) * IMGB + 64 * hf;
#pragma unroll
    for (int i = 0; i < 8; i++) {
        int h = 16 * w + 8 * rg + i;
        float4 v = make_float4(acc[i][0], acc[i][1], acc[i][2], acc[i][3]);
        *(float4*)&out[h * WW + cx * 4] = v;
    }
}

// ---------------------------------------------------------------------------
// Combine: one thread per output float4; 16 asm-forced independent LDG.128
// (ptxas cannot re-associate into a running sum -> full MLP), then
// noisy/clean/rot stores. 128 blocks x 128 threads = 16384 threads.
// ---------------------------------------------------------------------------
__global__ void __launch_bounds__(128) combine_kernel(const float* __restrict__ noise,
                                                      const float* __restrict__ rot,
                                                      float* __restrict__ out) {
    int tid = threadIdx.x;
    int o = blockIdx.x * 128 + tid;          // output float4 index, < IMG4

    float v[16][4];
#pragma unroll
    for (int i = 0; i < 16; i++) {
        const float4* ap = (const float4*)g_part + (i * 2) * IMG4 + o;
        asm volatile("ld.global.nc.v4.f32 {%0,%1,%2,%3}, [%4];"
                     : "=f"(v[i][0]), "=f"(v[i][1]), "=f"(v[i][2]), "=f"(v[i][3])
                     : "l"(ap));
    }
    // second 16 splits: reuse the same registers after folding
    float s0 = 0.f, s1 = 0.f, s2 = 0.f, s3 = 0.f;
#pragma unroll
    for (int i = 0; i < 16; i++) {
        s0 += v[i][0]; s1 += v[i][1]; s2 += v[i][2]; s3 += v[i][3];
    }
#pragma unroll
    for (int i = 0; i < 16; i++) {
        const float4* ap = (const float4*)g_part + (i * 2 + 1) * IMG4 + o;
        asm volatile("ld.global.nc.v4.f32 {%0,%1,%2,%3}, [%4];"
                     : "=f"(v[i][0]), "=f"(v[i][1]), "=f"(v[i][2]), "=f"(v[i][3])
                     : "l"(ap));
    }
#pragma unroll
    for (int i = 0; i < 16; i++) {
        s0 += v[i][0]; s1 += v[i][1]; s2 += v[i][2]; s3 += v[i][3];
    }

    float4 nz = ((const float4*)noise)[o];
    float4 noisy = make_float4(fmaf(nz.x, 0.1f, s0), fmaf(nz.y, 0.1f, s1),
                               fmaf(nz.z, 0.1f, s2), fmaf(nz.w, 0.1f, s3));
    ((float4*)out)[o] = noisy;                               // noisy
    *(float4*)&out[IMG + 36 + o * 4] = make_float4(s0, s1, s2, s3);  // clean
    if (blockIdx.x == 0 && tid < 36) out[IMG + tid] = rot[tid];
}

// ---------------------------------------------------------------------------
extern "C" void kernel_launch(void* const* d_in, const int* in_sizes, int n_in,
                              void* d_out, int out_size) {
    const float* x     = (const float*)d_in[0];  // (4,2048,3)
    const float* rot   = (const float*)d_in[1];  // (4,3,3)
    const float* noise = (const float*)d_in[2];  // (4,128,128)
    float* out = (float*)d_out;

    dim3 grid(SPLITS, BB, 2);
    fused_kernel<<<grid, 256>>>(x, rot);

    combine_kernel<<<IMG4 / 128, 128>>>(noise, rot, out);
}